// round 9
// baseline (speedup 1.0000x reference)
#include <cuda_runtime.h>
#include <math.h>

#define M_ANCH   589824
#define NCLS     80
#define K_TOP    1000
#define CAND_CAP 4096
#define NBINS    2048
#define GRID_P1  576
#define GRID_R   148
#define NTHR     256
#define NKEY4    (M_ANCH / 4)          /* 147456 */
#define RSTRIDE  (GRID_R * NTHR)       /* 37888 */
#define IMG_INV  (1.0f/2048.0f)
#define SCALE_CLAMP 4.1351665567423560f   /* log(1000/16) */

// ---------------- scratch (device globals; no allocations allowed) ----------
__device__ unsigned            g_key[M_ANCH];
__device__ unsigned            g_hist1[NBINS];
__device__ unsigned            g_hist2[NBINS];
__device__ unsigned            g_candCount;
__device__ unsigned long long  g_cand[CAND_CAP];
__device__ float4              g_boxes[K_TOP];
__device__ int                 g_labels[K_TOP];
__device__ unsigned            g_validw[32];     // 1000-bit valid bitset
__device__ unsigned            g_colnz[32];      // 1000-bit "column nonzero"
__device__ unsigned            g_mask[K_TOP * 32];
__device__ unsigned            g_barrier;        // starts 0; self-resets

// ---------------- helpers ---------------------------------------------------
__device__ __forceinline__ unsigned f2ord(float f) {
    unsigned u = __float_as_uint(f);
    return (u & 0x80000000u) ? ~u : (u | 0x80000000u);
}
// Sigmoid matching XLA lowering of lax.logistic on GPU (bit-stable vs ref).
__device__ __forceinline__ float ref_sigmoid(float x) {
    float e = expf(-x);
    return __fdiv_rn(1.0f, __fadd_rn(1.0f, e));
}

// grid barrier for GRID_R blocks with nanosleep backoff; sync #nfinal resets.
__device__ __forceinline__ void gridsync(int k, int nfinal) {
    __syncthreads();
    if (threadIdx.x == 0) {
        __threadfence();
        unsigned target = (unsigned)k * GRID_R;
        unsigned old = atomicAdd(&g_barrier, 1u);
        volatile unsigned* p = &g_barrier;
        if (k == nfinal) {
            if (old + 1u == target) {
                atomicExch(&g_barrier, 0u);
            } else {
                for (;;) {
                    unsigned v = *p;
                    if (v == 0u || v >= target) break;
                    __nanosleep(64);
                }
            }
        } else {
            while (*p < target) __nanosleep(64);
        }
        __threadfence();
    }
    __syncthreads();
}

// 256-thread find over a 2048-bin global hist: largest bin with
// base_extra + suffix(bin) >= K_TOP. Results in shared vars (all threads see).
__device__ void find_thresh(const unsigned* __restrict__ gh, unsigned base_extra,
                            unsigned* s_bin, unsigned* s_above) {
    __shared__ unsigned ssum[NTHR];
    __shared__ unsigned long long sbest;
    int t = threadIdx.x;
    unsigned h[8];
    unsigned s = 0;
#pragma unroll
    for (int e = 0; e < 8; e++) { h[e] = gh[t * 8 + e]; s += h[e]; }
    ssum[t] = s;
    if (t == 0) sbest = 0ULL;
    __syncthreads();
    for (int off = 1; off < NTHR; off <<= 1) {
        unsigned a = (t + off < NTHR) ? ssum[t + off] : 0u;
        __syncthreads();
        ssum[t] += a;
        __syncthreads();
    }
    unsigned run = ssum[t] - s;
    unsigned long long cand = 0ULL;
#pragma unroll
    for (int e = 7; e >= 0; e--) {
        run += h[e];
        if (base_extra + run >= K_TOP) {
            cand = ((unsigned long long)(t * 8 + e) << 32) | run;
            break;
        }
    }
    if (cand) atomicMax(&sbest, cand);
    __syncthreads();
    if (t == 0) {
        unsigned bin = (unsigned)(sbest >> 32);
        *s_bin = bin;
        if (s_above) *s_above = (unsigned)(sbest & 0xFFFFFFFFu) - gh[bin];
    }
    __syncthreads();
}

// ---------------- kernel 1: rowmax + hist1, software-pipelined ---------------
__global__ void __launch_bounds__(NTHR, 4)
k_p1(const float* __restrict__ cls) {
    __shared__ unsigned sh[NBINS];
    const int t = threadIdx.x;
    const int b = blockIdx.x;
    const int warpId = t >> 5;
    const int lane = t & 31;
    const int g = lane >> 2;
    const int gl = lane & 3;

    for (int e = t; e < NBINS; e += NTHR) sh[e] = 0u;
    __syncthreads();

    const int rowBase = b * 1024 + warpId * 128 + g;
    const float* basep = cls + (size_t)rowBase * NCLS + gl * 4;

    float4 A0, A1, A2, A3, A4;
    {
        const float* rp = basep;
        A0 = *(const float4*)(rp);
        A1 = *(const float4*)(rp + 16);
        A2 = *(const float4*)(rp + 32);
        A3 = *(const float4*)(rp + 48);
        A4 = *(const float4*)(rp + 64);
    }
#pragma unroll 2
    for (int p = 0; p < 16; p++) {
        int pn = (p < 15) ? p + 1 : 15;
        const float* rp = basep + (size_t)pn * 8 * NCLS;
        float4 B0 = *(const float4*)(rp);
        float4 B1 = *(const float4*)(rp + 16);
        float4 B2 = *(const float4*)(rp + 32);
        float4 B3 = *(const float4*)(rp + 48);
        float4 B4 = *(const float4*)(rp + 64);

        float m = fmaxf(fmaxf(A0.x, A0.y), fmaxf(A0.z, A0.w));
        m = fmaxf(m, fmaxf(fmaxf(A1.x, A1.y), fmaxf(A1.z, A1.w)));
        m = fmaxf(m, fmaxf(fmaxf(A2.x, A2.y), fmaxf(A2.z, A2.w)));
        m = fmaxf(m, fmaxf(fmaxf(A3.x, A3.y), fmaxf(A3.z, A3.w)));
        m = fmaxf(m, fmaxf(fmaxf(A4.x, A4.y), fmaxf(A4.z, A4.w)));
        m = fmaxf(m, __shfl_xor_sync(0xffffffffu, m, 1));
        m = fmaxf(m, __shfl_xor_sync(0xffffffffu, m, 2));
        if (gl == 0) {
            unsigned key = f2ord(ref_sigmoid(m));
            g_key[rowBase + p * 8] = key;
            atomicAdd(&sh[key >> 21], 1u);
        }
        A0 = B0; A1 = B1; A2 = B2; A3 = B3; A4 = B4;
    }
    __syncthreads();
    for (int e = t; e < NBINS; e += NTHR) {
        unsigned c = sh[e];
        if (c) atomicAdd(&g_hist1[e], c);
    }
}

// ---------------- kernel 2: find1+hist2 | find2+compact | rank+decode --------
__global__ void __launch_bounds__(NTHR, 4)
k_mid(const float* __restrict__ cls, const float* __restrict__ reg,
      const float* __restrict__ anc, float* __restrict__ out) {
    __shared__ unsigned sh[NBINS];
    __shared__ unsigned sB1, sAbove, sBin2;
    const int t = threadIdx.x;
    const int b = blockIdx.x;
    const int lane = t & 31;

    // ===== R1: find B1 (redundant per block); hist2 of bin B1 ===============
    unsigned B1, above;
    {
        if (b == 100 && t < 32) { g_validw[t] = 0u; g_colnz[t] = 0u; }
        find_thresh(g_hist1, 0u, &sB1, &sAbove);
        B1 = sB1; above = sAbove;
        for (int e = t; e < NBINS; e += NTHR) sh[e] = 0u;
        __syncthreads();
        const uint4* kp = (const uint4*)g_key;
#pragma unroll
        for (int it = 0; it < 4; it++) {
            int idx = b * NTHR + t + it * RSTRIDE;
            if (idx < NKEY4) {
                uint4 k4 = kp[idx];
                if ((k4.x >> 21) == B1) atomicAdd(&sh[(k4.x >> 10) & 2047u], 1u);
                if ((k4.y >> 21) == B1) atomicAdd(&sh[(k4.y >> 10) & 2047u], 1u);
                if ((k4.z >> 21) == B1) atomicAdd(&sh[(k4.z >> 10) & 2047u], 1u);
                if ((k4.w >> 21) == B1) atomicAdd(&sh[(k4.w >> 10) & 2047u], 1u);
            }
        }
        __syncthreads();
        for (int e = t; e < NBINS; e += NTHR) {
            unsigned c = sh[e];
            if (c) atomicAdd(&g_hist2[e], c);
        }
    }
    gridsync(1, 2);

    // ===== R2: find refined threshold; compact; zero hist1 ==================
    {
        find_thresh(g_hist2, above, &sBin2, 0);
        unsigned thr = (B1 << 21) | (sBin2 << 10);
        const uint4* kp = (const uint4*)g_key;
#pragma unroll
        for (int it = 0; it < 4; it++) {
            int idx = b * NTHR + t + it * RSTRIDE;
            bool inb = idx < NKEY4;
            uint4 k4 = inb ? kp[idx] : make_uint4(0u, 0u, 0u, 0u);
            int i0 = idx * 4;
            unsigned keys[4] = { k4.x, k4.y, k4.z, k4.w };
#pragma unroll
            for (int c = 0; c < 4; c++) {
                bool f = inb && (keys[c] >= thr);
                unsigned bal = __ballot_sync(0xffffffffu, f);
                if (bal) {
                    unsigned base;
                    if (lane == 0)
                        base = atomicAdd(&g_candCount, (unsigned)__popc(bal));
                    base = __shfl_sync(0xffffffffu, base, 0);
                    if (f) {
                        unsigned pos = base + __popc(bal & ((1u << lane) - 1u));
                        if (pos < CAND_CAP)
                            g_cand[pos] = ((unsigned long long)keys[c] << 32) |
                                          (unsigned)(~(i0 + c));
                    }
                }
            }
        }
        if (b >= 8 && b < 16) g_hist1[(b - 8) * NTHR + t] = 0u;
    }
    gridsync(2, 2);   // FINAL for k_mid: resets g_barrier

    // ===== R3: rank + decode; zero hist2 ====================================
    {
        unsigned cnt = min(g_candCount, (unsigned)CAND_CAP);
        unsigned id = b * NTHR + t;
        if ((unsigned)(b * NTHR) < cnt) {
            unsigned long long my = (id < cnt) ? g_cand[id] : 0ULL;
            unsigned rank = 0, jj = 0;
            for (; jj + 4 <= cnt; jj += 4) {
                unsigned long long a0 = g_cand[jj],     a1 = g_cand[jj + 1];
                unsigned long long a2 = g_cand[jj + 2], a3 = g_cand[jj + 3];
                rank += (a0 > my) + (a1 > my) + (a2 > my) + (a3 > my);
            }
            for (; jj < cnt; jj++) rank += (g_cand[jj] > my);
            if (id < cnt && rank < K_TOP) {
                int i = (int)(~(unsigned)(my & 0xFFFFFFFFULL));
                int j = (int)rank;
                const float4* row = (const float4*)(cls + (size_t)i * NCLS);
                float best = -1.0f; int bl = 0;
#pragma unroll
                for (int q = 0; q < NCLS / 4; q++) {
                    float4 v = row[q];
                    float s0 = ref_sigmoid(v.x), s1 = ref_sigmoid(v.y);
                    float s2 = ref_sigmoid(v.z), s3 = ref_sigmoid(v.w);
                    if (s0 > best) { best = s0; bl = 4 * q + 0; }
                    if (s1 > best) { best = s1; bl = 4 * q + 1; }
                    if (s2 > best) { best = s2; bl = 4 * q + 2; }
                    if (s3 > best) { best = s3; bl = 4 * q + 3; }
                }
                float4 rg = ((const float4*)reg)[i];
                float4 an = ((const float4*)anc)[i];
                float ox = fminf(fmaxf(rg.x * an.z, -32.0f), 32.0f);
                float oy = fminf(fmaxf(rg.y * an.w, -32.0f), 32.0f);
                float cx = an.x + ox, cy = an.y + oy;
                float w = an.z * expf(fminf(rg.z, SCALE_CLAMP));
                float h = an.w * expf(fminf(rg.w, SCALE_CLAMP));
                float x1 = fminf(fmaxf((cx - 0.5f * w) * IMG_INV, 0.0f), 1.0f);
                float y1 = fminf(fmaxf((cy - 0.5f * h) * IMG_INV, 0.0f), 1.0f);
                float x2 = fminf(fmaxf((cx + 0.5f * w) * IMG_INV, 0.0f), 1.0f);
                float y2 = fminf(fmaxf((cy + 0.5f * h) * IMG_INV, 0.0f), 1.0f);
                out[4 * j + 0] = x1; out[4 * j + 1] = y1;
                out[4 * j + 2] = x2; out[4 * j + 3] = y2;
                out[4000 + j] = best;
                out[5000 + j] = (float)bl;
                g_boxes[j] = make_float4(x1, y1, x2, y2);
                g_labels[j] = bl;
                if (best >= 0.05f)
                    atomicOr(&g_validw[j >> 5], 1u << (j & 31));
            }
        }
        if (b >= 16 && b < 24) g_hist2[(b - 16) * NTHR + t] = 0u;
    }
}

// ---------------- kernel 3: mask + sparse NMS --------------------------------
__global__ void __launch_bounds__(NTHR, 4)
k_end(float* __restrict__ out) {
    const int t = threadIdx.x;
    const int b = blockIdx.x;
    const int warpId = t >> 5;
    const int lane = t & 31;

    // mask + column-nonzero bitset
    {
        int gw = b * (NTHR / 32) + warpId;
        for (int task = gw; task < K_TOP * 32; task += GRID_R * (NTHR / 32)) {
            int i = task >> 5, W = task & 31;
            float4 bi = g_boxes[i];
            int li = g_labels[i];
            float ai = (bi.z - bi.x) * (bi.w - bi.y);
            int j = W * 32 + lane;
            bool sup = false;
            if (j < i && g_labels[j] == li) {
                float4 bj = g_boxes[j];
                float xx1 = fmaxf(bi.x, bj.x), yy1 = fmaxf(bi.y, bj.y);
                float xx2 = fminf(bi.z, bj.z), yy2 = fminf(bi.w, bj.w);
                float ww = fmaxf(1e-10f, xx2 - xx1);
                float hh = fmaxf(1e-10f, yy2 - yy1);
                float inter = ww * hh;
                float aj = (bj.z - bj.x) * (bj.w - bj.y);
                float iou = inter / (ai + aj - inter + 1e-10f);
                sup = iou > 0.6f;
            }
            unsigned bits = __ballot_sync(0xffffffffu, sup);
            if (lane == 0) {
                g_mask[task] = bits;
                if (bits) atomicOr(&g_colnz[i >> 5], 1u << (i & 31));
            }
        }
        if (b == 5 && t == 0) g_candCount = 0u;
    }
    gridsync(1, 1);   // FINAL: resets g_barrier

    // block0 sparse greedy NMS
    if (b == 0 && t < 32) {
        unsigned vw = g_validw[t];
        unsigned cz = g_colnz[t];
        unsigned kw = vw & ~cz;
        for (int w = 0; w < 32; w++) {
            unsigned word  = __shfl_sync(0xffffffffu, cz, w);
            unsigned vword = __shfl_sync(0xffffffffu, vw, w);
            while (word) {
                int bbit = __ffs(word) - 1;
                word &= word - 1u;
                int i = w * 32 + bbit;
                unsigned colw = g_mask[i * 32 + t];
                bool ov = __any_sync(0xffffffffu, (colw & kw) != 0u);
                bool kp = ((vword >> bbit) & 1u) && !ov;
                if (kp && t == w) kw |= (1u << bbit);
            }
        }
#pragma unroll
        for (int e = 0; e < 32; e++) {
            int i = t * 32 + e;
            if (i < K_TOP) out[6000 + i] = ((kw >> e) & 1u) ? 1.0f : 0.0f;
        }
    }
}

// ---------------- launcher ---------------------------------------------------
extern "C" void kernel_launch(void* const* d_in, const int* in_sizes, int n_in,
                              void* d_out, int out_size) {
    const float* cls = (const float*)d_in[0];
    const float* reg = (const float*)d_in[1];
    const float* anc = (const float*)d_in[2];
    float* out = (float*)d_out;
    (void)in_sizes; (void)n_in; (void)out_size;

    k_p1<<<GRID_P1, NTHR>>>(cls);
    k_mid<<<GRID_R, NTHR>>>(cls, reg, anc, out);
    k_end<<<GRID_R, NTHR>>>(out);
}

// round 10
// speedup vs baseline: 1.0664x; 1.0664x over previous
#include <cuda_runtime.h>
#include <math.h>

#define M_ANCH   589824
#define NCLS     80
#define K_TOP    1000
#define CAND_CAP 8192
#define HSHIFT   18                     /* 14-bit logit histogram */
#define NHBINS   16384
#define GRID_P1  576
#define GRID_R   148
#define NTHR     256
#define NKEY4    (M_ANCH / 4)           /* 147456 */
#define RSTRIDE  (GRID_R * NTHR)        /* 37888 */
#define IMG_INV  (1.0f/2048.0f)
#define SCALE_CLAMP 4.1351665567423560f /* log(1000/16) */

// ---------------- scratch (device globals; no allocations allowed) ----------
__device__ unsigned            g_key[M_ANCH];       // logit-ordered bits
__device__ unsigned            g_hist[NHBINS];      // starts 0; re-zeroed in K3
__device__ unsigned            g_candCount;
__device__ unsigned long long  g_cand[CAND_CAP];    // (sigmoid-key<<32)|~idx
__device__ float4              g_boxes[K_TOP];
__device__ int                 g_labels[K_TOP];
__device__ unsigned            g_validw[32];
__device__ unsigned            g_colnz[32];
__device__ unsigned            g_mask[K_TOP * 32];
__device__ unsigned            g_barrier;           // K4 only; self-resets

// ---------------- helpers ---------------------------------------------------
__device__ __forceinline__ unsigned f2ord(float f) {
    unsigned u = __float_as_uint(f);
    return (u & 0x80000000u) ? ~u : (u | 0x80000000u);
}
__device__ __forceinline__ float ord2f(unsigned o) {
    return (o & 0x80000000u) ? __uint_as_float(o & 0x7FFFFFFFu)
                             : __uint_as_float(~o);
}
// Sigmoid matching XLA lowering of lax.logistic on GPU (bit-stable vs ref).
__device__ __forceinline__ float ref_sigmoid(float x) {
    float e = expf(-x);
    return __fdiv_rn(1.0f, __fadd_rn(1.0f, e));
}

// grid barrier (K4 only, GRID_R blocks); final sync resets counter.
__device__ __forceinline__ void gridsync(int k, int nfinal) {
    __syncthreads();
    if (threadIdx.x == 0) {
        __threadfence();
        unsigned target = (unsigned)k * GRID_R;
        unsigned old = atomicAdd(&g_barrier, 1u);
        volatile unsigned* p = &g_barrier;
        if (k == nfinal) {
            if (old + 1u == target) {
                atomicExch(&g_barrier, 0u);
            } else {
                for (;;) {
                    unsigned v = *p;
                    if (v == 0u || v >= target) break;
                    __nanosleep(64);
                }
            }
        } else {
            while (*p < target) __nanosleep(64);
        }
        __threadfence();
    }
    __syncthreads();
}

// ---------------- K1: rowmax (pipelined) + logit key + 14-bit hist ----------
__global__ void __launch_bounds__(NTHR, 4)
k_p1(const float* __restrict__ cls) {
    __shared__ unsigned shp[NHBINS / 2];     // packed u16 pair counters, 32KB
    const int t = threadIdx.x;
    const int b = blockIdx.x;
    const int warpId = t >> 5;
    const int lane = t & 31;
    const int g = lane >> 2;
    const int gl = lane & 3;

    for (int e = t; e < NHBINS / 2; e += NTHR) shp[e] = 0u;
    __syncthreads();

    const int rowBase = b * 1024 + warpId * 128 + g;
    const float* basep = cls + (size_t)rowBase * NCLS + gl * 4;

    float4 A0, A1, A2, A3, A4;
    {
        const float* rp = basep;
        A0 = *(const float4*)(rp);
        A1 = *(const float4*)(rp + 16);
        A2 = *(const float4*)(rp + 32);
        A3 = *(const float4*)(rp + 48);
        A4 = *(const float4*)(rp + 64);
    }
#pragma unroll 2
    for (int p = 0; p < 16; p++) {
        int pn = (p < 15) ? p + 1 : 15;
        const float* rp = basep + (size_t)pn * 8 * NCLS;
        float4 B0 = *(const float4*)(rp);
        float4 B1 = *(const float4*)(rp + 16);
        float4 B2 = *(const float4*)(rp + 32);
        float4 B3 = *(const float4*)(rp + 48);
        float4 B4 = *(const float4*)(rp + 64);

        float m = fmaxf(fmaxf(A0.x, A0.y), fmaxf(A0.z, A0.w));
        m = fmaxf(m, fmaxf(fmaxf(A1.x, A1.y), fmaxf(A1.z, A1.w)));
        m = fmaxf(m, fmaxf(fmaxf(A2.x, A2.y), fmaxf(A2.z, A2.w)));
        m = fmaxf(m, fmaxf(fmaxf(A3.x, A3.y), fmaxf(A3.z, A3.w)));
        m = fmaxf(m, fmaxf(fmaxf(A4.x, A4.y), fmaxf(A4.z, A4.w)));
        m = fmaxf(m, __shfl_xor_sync(0xffffffffu, m, 1));
        m = fmaxf(m, __shfl_xor_sync(0xffffffffu, m, 2));
        if (gl == 0) {
            unsigned key = f2ord(m);           // logit-ordered (no sigmoid here)
            g_key[rowBase + p * 8] = key;
            unsigned bin = key >> HSHIFT;
            atomicAdd(&shp[bin >> 1], 1u << ((bin & 1u) << 4));
        }
        A0 = B0; A1 = B1; A2 = B2; A3 = B3; A4 = B4;
    }
    __syncthreads();
    for (int e = t; e < NHBINS / 2; e += NTHR) {
        unsigned v = shp[e];
        unsigned lo = v & 0xFFFFu, hi = v >> 16;
        if (lo) atomicAdd(&g_hist[2 * e], lo);
        if (hi) atomicAdd(&g_hist[2 * e + 1], hi);
    }
}

// ---------------- K2: find threshold (redundant per block) + compact --------
__global__ void __launch_bounds__(NTHR, 4)
k_sel() {
    __shared__ unsigned ssum[NTHR];
    __shared__ unsigned sbest;
    const int t = threadIdx.x;
    const int b = blockIdx.x;
    const int lane = t & 31;

    // find: thread t owns bins [t*64, t*64+64)
    unsigned s = 0;
    for (int e = 0; e < 64; e++) s += g_hist[t * 64 + e];
    ssum[t] = s;
    if (t == 0) sbest = 0u;
    __syncthreads();
    for (int off = 1; off < NTHR; off <<= 1) {
        unsigned a = (t + off < NTHR) ? ssum[t + off] : 0u;
        __syncthreads();
        ssum[t] += a;
        __syncthreads();
    }
    unsigned run = ssum[t] - s;              // strictly-higher threads' bins
    unsigned best = 0;
    for (int e = 63; e >= 0; e--) {
        run += g_hist[t * 64 + e];
        if (run >= K_TOP) { best = (unsigned)(t * 64 + e); break; }
    }
    if (best) atomicMax(&sbest, best);
    __syncthreads();
    unsigned B = sbest;
    unsigned thr = (B > 0 ? B - 1 : 0) << HSHIFT;   // one-bin tie margin

    // compact: grid-stride over keys; sigmoid computed only for candidates
    const uint4* kp = (const uint4*)g_key;
#pragma unroll
    for (int it = 0; it < 4; it++) {
        int idx = b * NTHR + t + it * RSTRIDE;
        bool inb = idx < NKEY4;
        uint4 k4 = inb ? kp[idx] : make_uint4(0u, 0u, 0u, 0u);
        int i0 = idx * 4;
        unsigned keys[4] = { k4.x, k4.y, k4.z, k4.w };
#pragma unroll
        for (int c = 0; c < 4; c++) {
            bool f = inb && (keys[c] >= thr);
            unsigned bal = __ballot_sync(0xffffffffu, f);
            if (bal) {
                unsigned base;
                if (lane == 0)
                    base = atomicAdd(&g_candCount, (unsigned)__popc(bal));
                base = __shfl_sync(0xffffffffu, base, 0);
                if (f) {
                    unsigned pos = base + __popc(bal & ((1u << lane) - 1u));
                    if (pos < CAND_CAP) {
                        unsigned skey = f2ord(ref_sigmoid(ord2f(keys[c])));
                        g_cand[pos] = ((unsigned long long)skey << 32) |
                                      (unsigned)(~(i0 + c));
                    }
                }
            }
        }
    }
    if (b == 100 && t < 32) g_validw[t] = 0u;
}

// ---------------- K3: rank (smem-staged) + decode; cleanup ------------------
__global__ void __launch_bounds__(NTHR, 2)
k_rank(const float* __restrict__ cls, const float* __restrict__ reg,
       const float* __restrict__ anc, float* __restrict__ out) {
    extern __shared__ unsigned long long sc[];
    const int t = threadIdx.x;
    const int b = blockIdx.x;
    unsigned cnt = min(g_candCount, (unsigned)CAND_CAP);

    if ((unsigned)(b * NTHR) < cnt) {
        for (unsigned j = t; j < cnt; j += NTHR) sc[j] = g_cand[j];
        __syncthreads();
        unsigned id = b * NTHR + t;
        if (id < cnt) {
            unsigned long long my = sc[id];
            unsigned rank = 0, jj = 0;
            for (; jj + 4 <= cnt; jj += 4) {
                rank += (sc[jj]     > my);
                rank += (sc[jj + 1] > my);
                rank += (sc[jj + 2] > my);
                rank += (sc[jj + 3] > my);
            }
            for (; jj < cnt; jj++) rank += (sc[jj] > my);
            if (rank < K_TOP) {
                int i = (int)(~(unsigned)(my & 0xFFFFFFFFULL));
                int j = (int)rank;
                const float4* row = (const float4*)(cls + (size_t)i * NCLS);
                float best = -1.0f; int bl = 0;
#pragma unroll
                for (int q = 0; q < NCLS / 4; q++) {
                    float4 v = row[q];
                    float s0 = ref_sigmoid(v.x), s1 = ref_sigmoid(v.y);
                    float s2 = ref_sigmoid(v.z), s3 = ref_sigmoid(v.w);
                    if (s0 > best) { best = s0; bl = 4 * q + 0; }
                    if (s1 > best) { best = s1; bl = 4 * q + 1; }
                    if (s2 > best) { best = s2; bl = 4 * q + 2; }
                    if (s3 > best) { best = s3; bl = 4 * q + 3; }
                }
                float4 rg = ((const float4*)reg)[i];
                float4 an = ((const float4*)anc)[i];
                float ox = fminf(fmaxf(rg.x * an.z, -32.0f), 32.0f);
                float oy = fminf(fmaxf(rg.y * an.w, -32.0f), 32.0f);
                float cx = an.x + ox, cy = an.y + oy;
                float w = an.z * expf(fminf(rg.z, SCALE_CLAMP));
                float h = an.w * expf(fminf(rg.w, SCALE_CLAMP));
                float x1 = fminf(fmaxf((cx - 0.5f * w) * IMG_INV, 0.0f), 1.0f);
                float y1 = fminf(fmaxf((cy - 0.5f * h) * IMG_INV, 0.0f), 1.0f);
                float x2 = fminf(fmaxf((cx + 0.5f * w) * IMG_INV, 0.0f), 1.0f);
                float y2 = fminf(fmaxf((cy + 0.5f * h) * IMG_INV, 0.0f), 1.0f);
                out[4 * j + 0] = x1; out[4 * j + 1] = y1;
                out[4 * j + 2] = x2; out[4 * j + 3] = y2;
                out[4000 + j] = best;
                out[5000 + j] = (float)bl;
                g_boxes[j] = make_float4(x1, y1, x2, y2);
                g_labels[j] = bl;
                if (best >= 0.05f)
                    atomicOr(&g_validw[j >> 5], 1u << (j & 31));
            }
        }
    }
    // cleanup for next run: hist (32 blocks x 256 x 2 = 16384) + colnz
    int z = b * NTHR + t;
    g_hist[2 * z] = 0u; g_hist[2 * z + 1] = 0u;
    if (b == 0 && t < 32) g_colnz[t] = 0u;
}

// ---------------- K4: mask + sync + sparse NMS ------------------------------
__global__ void __launch_bounds__(NTHR, 4)
k_end(float* __restrict__ out) {
    const int t = threadIdx.x;
    const int b = blockIdx.x;
    const int warpId = t >> 5;
    const int lane = t & 31;

    {
        int gw = b * (NTHR / 32) + warpId;
        for (int task = gw; task < K_TOP * 32; task += GRID_R * (NTHR / 32)) {
            int i = task >> 5, W = task & 31;
            float4 bi = g_boxes[i];
            int li = g_labels[i];
            float ai = (bi.z - bi.x) * (bi.w - bi.y);
            int j = W * 32 + lane;
            bool sup = false;
            if (j < i && g_labels[j] == li) {
                float4 bj = g_boxes[j];
                float xx1 = fmaxf(bi.x, bj.x), yy1 = fmaxf(bi.y, bj.y);
                float xx2 = fminf(bi.z, bj.z), yy2 = fminf(bi.w, bj.w);
                float ww = fmaxf(1e-10f, xx2 - xx1);
                float hh = fmaxf(1e-10f, yy2 - yy1);
                float inter = ww * hh;
                float aj = (bj.z - bj.x) * (bj.w - bj.y);
                float iou = inter / (ai + aj - inter + 1e-10f);
                sup = iou > 0.6f;
            }
            unsigned bits = __ballot_sync(0xffffffffu, sup);
            if (lane == 0) {
                g_mask[task] = bits;
                if (bits) atomicOr(&g_colnz[i >> 5], 1u << (i & 31));
            }
        }
        if (b == 5 && t == 0) g_candCount = 0u;
    }
    gridsync(1, 1);   // FINAL: resets g_barrier

    if (b == 0 && t < 32) {
        unsigned vw = g_validw[t];
        unsigned cz = g_colnz[t];
        unsigned kw = vw & ~cz;
        for (int w = 0; w < 32; w++) {
            unsigned word  = __shfl_sync(0xffffffffu, cz, w);
            unsigned vword = __shfl_sync(0xffffffffu, vw, w);
            while (word) {
                int bbit = __ffs(word) - 1;
                word &= word - 1u;
                int i = w * 32 + bbit;
                unsigned colw = g_mask[i * 32 + t];
                bool ov = __any_sync(0xffffffffu, (colw & kw) != 0u);
                bool kp = ((vword >> bbit) & 1u) && !ov;
                if (kp && t == w) kw |= (1u << bbit);
            }
        }
#pragma unroll
        for (int e = 0; e < 32; e++) {
            int i = t * 32 + e;
            if (i < K_TOP) out[6000 + i] = ((kw >> e) & 1u) ? 1.0f : 0.0f;
        }
    }
}

// ---------------- launcher ---------------------------------------------------
extern "C" void kernel_launch(void* const* d_in, const int* in_sizes, int n_in,
                              void* d_out, int out_size) {
    const float* cls = (const float*)d_in[0];
    const float* reg = (const float*)d_in[1];
    const float* anc = (const float*)d_in[2];
    float* out = (float*)d_out;
    (void)in_sizes; (void)n_in; (void)out_size;

    cudaFuncSetAttribute(k_rank, cudaFuncAttributeMaxDynamicSharedMemorySize,
                         CAND_CAP * (int)sizeof(unsigned long long));

    k_p1<<<GRID_P1, NTHR>>>(cls);
    k_sel<<<GRID_R, NTHR>>>();
    k_rank<<<32, NTHR, CAND_CAP * sizeof(unsigned long long)>>>(cls, reg, anc, out);
    k_end<<<GRID_R, NTHR>>>(out);
}

// round 11
// speedup vs baseline: 1.3831x; 1.2970x over previous
#include <cuda_runtime.h>
#include <math.h>

#define M_ANCH   589824
#define NCLS     80
#define K_TOP    1000
#define CAND_CAP 8192
#define HSHIFT   18                     /* 14-bit logit histogram */
#define NHBINS   16384
#define GRID_P1  576
#define GRID_R   148
#define NTHR     256
#define NWARPS   (GRID_R * (NTHR / 32)) /* 1184 */
#define NKEY4    (M_ANCH / 4)           /* 147456 */
#define RSTRIDE  (GRID_R * NTHR)        /* 37888 */
#define CAPC     256                    /* staged NMS columns */
#define IMG_INV  (1.0f/2048.0f)
#define SCALE_CLAMP 4.1351665567423560f /* log(1000/16) */

// ---------------- scratch (device globals; no allocations allowed) ----------
__device__ unsigned            g_key[M_ANCH];       // logit-ordered bits
__device__ unsigned            g_hist[NHBINS];      // starts 0; re-zeroed in K3
__device__ unsigned            g_candCount;
__device__ unsigned long long  g_cand[CAND_CAP];    // (sigmoid-key<<32)|~idx
__device__ float4              g_boxes[K_TOP];
__device__ int                 g_labels[K_TOP];
__device__ unsigned            g_validw[32];
__device__ unsigned            g_colnz[32];
__device__ unsigned            g_mask[K_TOP * 32];
__device__ unsigned            g_barrier;           // K4 only; self-resets

// ---------------- helpers ---------------------------------------------------
__device__ __forceinline__ unsigned f2ord(float f) {
    unsigned u = __float_as_uint(f);
    return (u & 0x80000000u) ? ~u : (u | 0x80000000u);
}
__device__ __forceinline__ float ord2f(unsigned o) {
    return (o & 0x80000000u) ? __uint_as_float(o & 0x7FFFFFFFu)
                             : __uint_as_float(~o);
}
// Sigmoid matching XLA lowering of lax.logistic on GPU (bit-stable vs ref).
__device__ __forceinline__ float ref_sigmoid(float x) {
    float e = expf(-x);
    return __fdiv_rn(1.0f, __fadd_rn(1.0f, e));
}

__device__ __forceinline__ void gridsync(int k, int nfinal) {
    __syncthreads();
    if (threadIdx.x == 0) {
        __threadfence();
        unsigned target = (unsigned)k * GRID_R;
        unsigned old = atomicAdd(&g_barrier, 1u);
        volatile unsigned* p = &g_barrier;
        if (k == nfinal) {
            if (old + 1u == target) {
                atomicExch(&g_barrier, 0u);
            } else {
                for (;;) {
                    unsigned v = *p;
                    if (v == 0u || v >= target) break;
                    __nanosleep(64);
                }
            }
        } else {
            while (*p < target) __nanosleep(64);
        }
        __threadfence();
    }
    __syncthreads();
}

// ---------------- K1: rowmax (pipelined) + logit key + 14-bit hist ----------
__global__ void __launch_bounds__(NTHR, 4)
k_p1(const float* __restrict__ cls) {
    __shared__ unsigned shp[NHBINS / 2];     // packed u16 pair counters, 32KB
    const int t = threadIdx.x;
    const int b = blockIdx.x;
    const int warpId = t >> 5;
    const int lane = t & 31;
    const int g = lane >> 2;
    const int gl = lane & 3;

    for (int e = t; e < NHBINS / 2; e += NTHR) shp[e] = 0u;
    __syncthreads();

    const int rowBase = b * 1024 + warpId * 128 + g;
    const float* basep = cls + (size_t)rowBase * NCLS + gl * 4;

    float4 A0, A1, A2, A3, A4;
    {
        const float* rp = basep;
        A0 = *(const float4*)(rp);
        A1 = *(const float4*)(rp + 16);
        A2 = *(const float4*)(rp + 32);
        A3 = *(const float4*)(rp + 48);
        A4 = *(const float4*)(rp + 64);
    }
#pragma unroll 2
    for (int p = 0; p < 16; p++) {
        int pn = (p < 15) ? p + 1 : 15;
        const float* rp = basep + (size_t)pn * 8 * NCLS;
        float4 B0 = *(const float4*)(rp);
        float4 B1 = *(const float4*)(rp + 16);
        float4 B2 = *(const float4*)(rp + 32);
        float4 B3 = *(const float4*)(rp + 48);
        float4 B4 = *(const float4*)(rp + 64);

        float m = fmaxf(fmaxf(A0.x, A0.y), fmaxf(A0.z, A0.w));
        m = fmaxf(m, fmaxf(fmaxf(A1.x, A1.y), fmaxf(A1.z, A1.w)));
        m = fmaxf(m, fmaxf(fmaxf(A2.x, A2.y), fmaxf(A2.z, A2.w)));
        m = fmaxf(m, fmaxf(fmaxf(A3.x, A3.y), fmaxf(A3.z, A3.w)));
        m = fmaxf(m, fmaxf(fmaxf(A4.x, A4.y), fmaxf(A4.z, A4.w)));
        m = fmaxf(m, __shfl_xor_sync(0xffffffffu, m, 1));
        m = fmaxf(m, __shfl_xor_sync(0xffffffffu, m, 2));
        if (gl == 0) {
            unsigned key = f2ord(m);
            g_key[rowBase + p * 8] = key;
            unsigned bin = key >> HSHIFT;
            atomicAdd(&shp[bin >> 1], 1u << ((bin & 1u) << 4));
        }
        A0 = B0; A1 = B1; A2 = B2; A3 = B3; A4 = B4;
    }
    __syncthreads();
    for (int e = t; e < NHBINS / 2; e += NTHR) {
        unsigned v = shp[e];
        unsigned lo = v & 0xFFFFu, hi = v >> 16;
        if (lo) atomicAdd(&g_hist[2 * e], lo);
        if (hi) atomicAdd(&g_hist[2 * e + 1], hi);
    }
}

// ---------------- K2: find threshold (redundant per block) + compact --------
__global__ void __launch_bounds__(NTHR, 4)
k_sel() {
    __shared__ unsigned ssum[NTHR];
    __shared__ unsigned sbest;
    const int t = threadIdx.x;
    const int b = blockIdx.x;
    const int lane = t & 31;

    unsigned s = 0;
#pragma unroll 8
    for (int e = 0; e < 64; e++) s += g_hist[t * 64 + e];
    ssum[t] = s;
    if (t == 0) sbest = 0u;
    __syncthreads();
    for (int off = 1; off < NTHR; off <<= 1) {
        unsigned a = (t + off < NTHR) ? ssum[t + off] : 0u;
        __syncthreads();
        ssum[t] += a;
        __syncthreads();
    }
    unsigned run = ssum[t] - s;
    unsigned best = 0;
    for (int e = 63; e >= 0; e--) {
        run += g_hist[t * 64 + e];
        if (run >= K_TOP) { best = (unsigned)(t * 64 + e); break; }
    }
    if (best) atomicMax(&sbest, best);
    __syncthreads();
    unsigned B = sbest;
    unsigned thr = (B > 0 ? B - 1 : 0) << HSHIFT;   // one-bin tie margin

    const uint4* kp = (const uint4*)g_key;
#pragma unroll
    for (int it = 0; it < 4; it++) {
        int idx = b * NTHR + t + it * RSTRIDE;
        bool inb = idx < NKEY4;
        uint4 k4 = inb ? kp[idx] : make_uint4(0u, 0u, 0u, 0u);
        int i0 = idx * 4;
        unsigned keys[4] = { k4.x, k4.y, k4.z, k4.w };
#pragma unroll
        for (int c = 0; c < 4; c++) {
            bool f = inb && (keys[c] >= thr);
            unsigned bal = __ballot_sync(0xffffffffu, f);
            if (bal) {
                unsigned base;
                if (lane == 0)
                    base = atomicAdd(&g_candCount, (unsigned)__popc(bal));
                base = __shfl_sync(0xffffffffu, base, 0);
                if (f) {
                    unsigned pos = base + __popc(bal & ((1u << lane) - 1u));
                    if (pos < CAND_CAP) {
                        unsigned skey = f2ord(ref_sigmoid(ord2f(keys[c])));
                        g_cand[pos] = ((unsigned long long)skey << 32) |
                                      (unsigned)(~(i0 + c));
                    }
                }
            }
        }
    }
    if (b == 100 && t < 32) g_validw[t] = 0u;
}

// ---------------- K3: warp-per-candidate rank + cooperative decode ----------
__global__ void __launch_bounds__(NTHR, 2)
k_rank(const float* __restrict__ cls, const float* __restrict__ reg,
       const float* __restrict__ anc, float* __restrict__ out) {
    extern __shared__ unsigned long long sc[];
    const int t = threadIdx.x;
    const int b = blockIdx.x;
    const int warpId = t >> 5;
    const int lane = t & 31;
    unsigned cnt = min(g_candCount, (unsigned)CAND_CAP);

    for (unsigned j = t; j < cnt; j += NTHR) sc[j] = g_cand[j];
    __syncthreads();

    int gw = b * (NTHR / 32) + warpId;
    for (unsigned c = (unsigned)gw; c < cnt; c += NWARPS) {
        unsigned long long my = sc[c];
        unsigned r = 0;
        for (unsigned j = lane; j < cnt; j += 32) r += (sc[j] > my);
        r = __reduce_add_sync(0xffffffffu, r);
        if (r < K_TOP) {
            int i = (int)(~(unsigned)(my & 0xFFFFFFFFULL));
            int j = (int)r;
            // cooperative argmax over 80 classes: lanes 0-19 own 4 each
            const float4* row = (const float4*)(cls + (size_t)i * NCLS);
            unsigned long long bkey = 0ULL;
            if (lane < NCLS / 4) {
                float4 v = row[lane];
                float s0 = ref_sigmoid(v.x), s1 = ref_sigmoid(v.y);
                float s2 = ref_sigmoid(v.z), s3 = ref_sigmoid(v.w);
                unsigned long long k0 = ((unsigned long long)f2ord(s0) << 32) |
                                        (unsigned)(~(4 * lane + 0));
                unsigned long long k1 = ((unsigned long long)f2ord(s1) << 32) |
                                        (unsigned)(~(4 * lane + 1));
                unsigned long long k2 = ((unsigned long long)f2ord(s2) << 32) |
                                        (unsigned)(~(4 * lane + 2));
                unsigned long long k3 = ((unsigned long long)f2ord(s3) << 32) |
                                        (unsigned)(~(4 * lane + 3));
                bkey = max(max(k0, k1), max(k2, k3));
            }
#pragma unroll
            for (int off = 16; off >= 1; off >>= 1) {
                unsigned long long o = __shfl_xor_sync(0xffffffffu, bkey, off);
                if (o > bkey) bkey = o;
            }
            if (lane == 0) {
                float best = ord2f((unsigned)(bkey >> 32));
                int bl = (int)(~(unsigned)(bkey & 0xFFFFFFFFULL));
                float4 rg = ((const float4*)reg)[i];
                float4 an = ((const float4*)anc)[i];
                float ox = fminf(fmaxf(rg.x * an.z, -32.0f), 32.0f);
                float oy = fminf(fmaxf(rg.y * an.w, -32.0f), 32.0f);
                float cx = an.x + ox, cy = an.y + oy;
                float w = an.z * expf(fminf(rg.z, SCALE_CLAMP));
                float h = an.w * expf(fminf(rg.w, SCALE_CLAMP));
                float x1 = fminf(fmaxf((cx - 0.5f * w) * IMG_INV, 0.0f), 1.0f);
                float y1 = fminf(fmaxf((cy - 0.5f * h) * IMG_INV, 0.0f), 1.0f);
                float x2 = fminf(fmaxf((cx + 0.5f * w) * IMG_INV, 0.0f), 1.0f);
                float y2 = fminf(fmaxf((cy + 0.5f * h) * IMG_INV, 0.0f), 1.0f);
                out[4 * j + 0] = x1; out[4 * j + 1] = y1;
                out[4 * j + 2] = x2; out[4 * j + 3] = y2;
                out[4000 + j] = best;
                out[5000 + j] = (float)bl;
                g_boxes[j] = make_float4(x1, y1, x2, y2);
                g_labels[j] = bl;
                if (best >= 0.05f)
                    atomicOr(&g_validw[j >> 5], 1u << (j & 31));
            }
        }
    }
    // cleanup for next run: hist + colnz
    {
        int z = b * NTHR + t;
        if (z < NHBINS) g_hist[z] = 0u;
        if (b == 0 && t < 32) g_colnz[t] = 0u;
    }
}

// ---------------- K4: mask + sync + smem-staged sparse NMS ------------------
__global__ void __launch_bounds__(NTHR, 4)
k_end(float* __restrict__ out) {
    __shared__ unsigned s_list[K_TOP > 1024 ? K_TOP : 1024];
    __shared__ unsigned s_cols[CAPC * 32];
    __shared__ unsigned s_C;
    const int t = threadIdx.x;
    const int b = blockIdx.x;
    const int warpId = t >> 5;
    const int lane = t & 31;

    // mask + column-nonzero bitset
    {
        int gw = b * (NTHR / 32) + warpId;
        for (int task = gw; task < K_TOP * 32; task += GRID_R * (NTHR / 32)) {
            int i = task >> 5, W = task & 31;
            float4 bi = g_boxes[i];
            int li = g_labels[i];
            float ai = (bi.z - bi.x) * (bi.w - bi.y);
            int j = W * 32 + lane;
            bool sup = false;
            if (j < i && g_labels[j] == li) {
                float4 bj = g_boxes[j];
                float xx1 = fmaxf(bi.x, bj.x), yy1 = fmaxf(bi.y, bj.y);
                float xx2 = fminf(bi.z, bj.z), yy2 = fminf(bi.w, bj.w);
                float ww = fmaxf(1e-10f, xx2 - xx1);
                float hh = fmaxf(1e-10f, yy2 - yy1);
                float inter = ww * hh;
                float aj = (bj.z - bj.x) * (bj.w - bj.y);
                float iou = inter / (ai + aj - inter + 1e-10f);
                sup = iou > 0.6f;
            }
            unsigned bits = __ballot_sync(0xffffffffu, sup);
            if (lane == 0) {
                g_mask[task] = bits;
                if (bits) atomicOr(&g_colnz[i >> 5], 1u << (i & 31));
            }
        }
        if (b == 5 && t == 0) g_candCount = 0u;
    }
    gridsync(1, 1);   // FINAL: resets g_barrier
    if (b != 0) return;

    // build ordered nonzero-column list (warp 0)
    if (t < 32) {
        unsigned cz = g_colnz[t];
        unsigned pc = __popc(cz);
        unsigned pre = pc;
#pragma unroll
        for (int off = 1; off < 32; off <<= 1) {
            unsigned v = __shfl_up_sync(0xffffffffu, pre, off);
            if (lane >= off) pre += v;
        }
        unsigned start = pre - pc;              // exclusive prefix
        unsigned word = cz, k = 0;
        while (word) {
            int bbit = __ffs(word) - 1;
            word &= word - 1u;
            s_list[start + k] = (unsigned)(t * 32 + bbit);
            k++;
        }
        if (t == 31) s_C = pre;
    }
    __syncthreads();
    unsigned C = s_C;

    // stage the first min(C, CAPC) columns into smem (all 256 threads)
    unsigned CS = min(C, (unsigned)CAPC);
    for (unsigned idx = t; idx < CS * 32; idx += NTHR) {
        unsigned k = idx >> 5, l2 = idx & 31;
        s_cols[idx] = g_mask[s_list[k] * 32 + l2];
    }
    __syncthreads();

    // serial greedy over nonzero columns only (warp 0)
    if (t < 32) {
        unsigned vw = g_validw[t];
        unsigned cz = g_colnz[t];
        unsigned kw = vw & ~cz;                 // zero-column: keep = valid
        for (unsigned k = 0; k < C; k++) {
            unsigned i = s_list[k];
            unsigned colw = (k < CAPC) ? s_cols[k * 32 + t]
                                       : g_mask[i * 32 + t];
            bool ov = __any_sync(0xffffffffu, (colw & kw) != 0u);
            unsigned vb = (__shfl_sync(0xffffffffu, vw, i >> 5) >> (i & 31)) & 1u;
            bool kp = (vb != 0u) && !ov;
            if (kp && (unsigned)t == (i >> 5)) kw |= (1u << (i & 31));
        }
#pragma unroll
        for (int e = 0; e < 32; e++) {
            int i = t * 32 + e;
            if (i < K_TOP) out[6000 + i] = ((kw >> e) & 1u) ? 1.0f : 0.0f;
        }
    }
}

// ---------------- launcher ---------------------------------------------------
extern "C" void kernel_launch(void* const* d_in, const int* in_sizes, int n_in,
                              void* d_out, int out_size) {
    const float* cls = (const float*)d_in[0];
    const float* reg = (const float*)d_in[1];
    const float* anc = (const float*)d_in[2];
    float* out = (float*)d_out;
    (void)in_sizes; (void)n_in; (void)out_size;

    cudaFuncSetAttribute(k_rank, cudaFuncAttributeMaxDynamicSharedMemorySize,
                         CAND_CAP * (int)sizeof(unsigned long long));

    k_p1<<<GRID_P1, NTHR>>>(cls);
    k_sel<<<GRID_R, NTHR>>>();
    k_rank<<<GRID_R, NTHR, CAND_CAP * sizeof(unsigned long long)>>>(cls, reg, anc, out);
    k_end<<<GRID_R, NTHR>>>(out);
}

// round 12
// speedup vs baseline: 1.3961x; 1.0094x over previous
#include <cuda_runtime.h>
#include <math.h>

#define M_ANCH   589824
#define NCLS     80
#define K_TOP    1000
#define CAND_CAP 8192
#define HSHIFT   18                     /* 14-bit logit histogram */
#define NHBINS   16384
#define GRID_P1  576
#define GRID_R   148
#define NTHR     256
#define NWARPS   (GRID_R * (NTHR / 32)) /* 1184 */
#define NKEY4    (M_ANCH / 4)           /* 147456 */
#define RSTRIDE  (GRID_R * NTHR)        /* 37888 */
#define CAPC     128                    /* staged NMS columns */
#define IMG_INV  (1.0f/2048.0f)
#define SCALE_CLAMP 4.1351665567423560f /* log(1000/16) */

// ---------------- scratch (device globals; no allocations allowed) ----------
__device__ unsigned            g_key[M_ANCH];       // logit-ordered bits
__device__ unsigned            g_hist[NHBINS];      // starts 0; re-zeroed in K3
__device__ unsigned            g_candCount;
__device__ unsigned long long  g_cand[CAND_CAP];    // (sigmoid-key<<32)|~idx
__device__ float4              g_boxes[K_TOP];
__device__ int                 g_labels[K_TOP];
__device__ unsigned            g_validw[32];
__device__ unsigned            g_colnz[32];
__device__ unsigned            g_mask[K_TOP * 32];
__device__ unsigned            g_barrier;           // K4 only; self-resets

// ---------------- helpers ---------------------------------------------------
__device__ __forceinline__ unsigned f2ord(float f) {
    unsigned u = __float_as_uint(f);
    return (u & 0x80000000u) ? ~u : (u | 0x80000000u);
}
__device__ __forceinline__ float ord2f(unsigned o) {
    return (o & 0x80000000u) ? __uint_as_float(o & 0x7FFFFFFFu)
                             : __uint_as_float(~o);
}
// Sigmoid matching XLA lowering of lax.logistic on GPU (bit-stable vs ref).
__device__ __forceinline__ float ref_sigmoid(float x) {
    float e = expf(-x);
    return __fdiv_rn(1.0f, __fadd_rn(1.0f, e));
}

__device__ __forceinline__ void gridsync(int k, int nfinal) {
    __syncthreads();
    if (threadIdx.x == 0) {
        __threadfence();
        unsigned target = (unsigned)k * GRID_R;
        unsigned old = atomicAdd(&g_barrier, 1u);
        volatile unsigned* p = &g_barrier;
        if (k == nfinal) {
            if (old + 1u == target) {
                atomicExch(&g_barrier, 0u);
            } else {
                for (;;) {
                    unsigned v = *p;
                    if (v == 0u || v >= target) break;
                    __nanosleep(64);
                }
            }
        } else {
            while (*p < target) __nanosleep(64);
        }
        __threadfence();
    }
    __syncthreads();
}

// ---------------- K1: rowmax (pipelined) + logit key + 14-bit hist ----------
__global__ void __launch_bounds__(NTHR, 4)
k_p1(const float* __restrict__ cls) {
    __shared__ unsigned shp[NHBINS / 2];     // packed u16 pair counters, 32KB
    const int t = threadIdx.x;
    const int b = blockIdx.x;
    const int warpId = t >> 5;
    const int lane = t & 31;
    const int g = lane >> 2;
    const int gl = lane & 3;

    for (int e = t; e < NHBINS / 2; e += NTHR) shp[e] = 0u;
    __syncthreads();

    const int rowBase = b * 1024 + warpId * 128 + g;
    const float* basep = cls + (size_t)rowBase * NCLS + gl * 4;

    float4 A0, A1, A2, A3, A4;
    {
        const float* rp = basep;
        A0 = *(const float4*)(rp);
        A1 = *(const float4*)(rp + 16);
        A2 = *(const float4*)(rp + 32);
        A3 = *(const float4*)(rp + 48);
        A4 = *(const float4*)(rp + 64);
    }
#pragma unroll 2
    for (int p = 0; p < 16; p++) {
        int pn = (p < 15) ? p + 1 : 15;
        const float* rp = basep + (size_t)pn * 8 * NCLS;
        float4 B0 = *(const float4*)(rp);
        float4 B1 = *(const float4*)(rp + 16);
        float4 B2 = *(const float4*)(rp + 32);
        float4 B3 = *(const float4*)(rp + 48);
        float4 B4 = *(const float4*)(rp + 64);

        float m = fmaxf(fmaxf(A0.x, A0.y), fmaxf(A0.z, A0.w));
        m = fmaxf(m, fmaxf(fmaxf(A1.x, A1.y), fmaxf(A1.z, A1.w)));
        m = fmaxf(m, fmaxf(fmaxf(A2.x, A2.y), fmaxf(A2.z, A2.w)));
        m = fmaxf(m, fmaxf(fmaxf(A3.x, A3.y), fmaxf(A3.z, A3.w)));
        m = fmaxf(m, fmaxf(fmaxf(A4.x, A4.y), fmaxf(A4.z, A4.w)));
        m = fmaxf(m, __shfl_xor_sync(0xffffffffu, m, 1));
        m = fmaxf(m, __shfl_xor_sync(0xffffffffu, m, 2));
        if (gl == 0) {
            unsigned key = f2ord(m);
            g_key[rowBase + p * 8] = key;
            unsigned bin = key >> HSHIFT;
            atomicAdd(&shp[bin >> 1], 1u << ((bin & 1u) << 4));
        }
        A0 = B0; A1 = B1; A2 = B2; A3 = B3; A4 = B4;
    }
    __syncthreads();
    for (int e = t; e < NHBINS / 2; e += NTHR) {
        unsigned v = shp[e];
        unsigned lo = v & 0xFFFFu, hi = v >> 16;
        if (lo) atomicAdd(&g_hist[2 * e], lo);
        if (hi) atomicAdd(&g_hist[2 * e + 1], hi);
    }
}

// ---------------- K2: find threshold (redundant per block) + compact --------
__global__ void __launch_bounds__(NTHR, 4)
k_sel() {
    __shared__ unsigned ssum[NTHR];
    __shared__ unsigned sbest;
    const int t = threadIdx.x;
    const int b = blockIdx.x;
    const int lane = t & 31;

    unsigned s = 0;
#pragma unroll 8
    for (int e = 0; e < 64; e++) s += g_hist[t * 64 + e];
    ssum[t] = s;
    if (t == 0) sbest = 0u;
    __syncthreads();
    for (int off = 1; off < NTHR; off <<= 1) {
        unsigned a = (t + off < NTHR) ? ssum[t + off] : 0u;
        __syncthreads();
        ssum[t] += a;
        __syncthreads();
    }
    unsigned run = ssum[t] - s;
    unsigned best = 0;
    for (int e = 63; e >= 0; e--) {
        run += g_hist[t * 64 + e];
        if (run >= K_TOP) { best = (unsigned)(t * 64 + e); break; }
    }
    if (best) atomicMax(&sbest, best);
    __syncthreads();
    unsigned B = sbest;
    unsigned thr = (B > 0 ? B - 1 : 0) << HSHIFT;   // one-bin tie margin

    const uint4* kp = (const uint4*)g_key;
#pragma unroll
    for (int it = 0; it < 4; it++) {
        int idx = b * NTHR + t + it * RSTRIDE;
        bool inb = idx < NKEY4;
        uint4 k4 = inb ? kp[idx] : make_uint4(0u, 0u, 0u, 0u);
        int i0 = idx * 4;
        unsigned keys[4] = { k4.x, k4.y, k4.z, k4.w };
#pragma unroll
        for (int c = 0; c < 4; c++) {
            bool f = inb && (keys[c] >= thr);
            unsigned bal = __ballot_sync(0xffffffffu, f);
            if (bal) {
                unsigned base;
                if (lane == 0)
                    base = atomicAdd(&g_candCount, (unsigned)__popc(bal));
                base = __shfl_sync(0xffffffffu, base, 0);
                if (f) {
                    unsigned pos = base + __popc(bal & ((1u << lane) - 1u));
                    if (pos < CAND_CAP) {
                        unsigned skey = f2ord(ref_sigmoid(ord2f(keys[c])));
                        g_cand[pos] = ((unsigned long long)skey << 32) |
                                      (unsigned)(~(i0 + c));
                    }
                }
            }
        }
    }
    if (b == 100 && t < 32) g_validw[t] = 0u;
}

// ---------------- K3: warp-per-candidate rank + cooperative decode ----------
__global__ void __launch_bounds__(NTHR, 2)
k_rank(const float* __restrict__ cls, const float* __restrict__ reg,
       const float* __restrict__ anc, float* __restrict__ out) {
    extern __shared__ unsigned long long sc[];
    const int t = threadIdx.x;
    const int b = blockIdx.x;
    const int warpId = t >> 5;
    const int lane = t & 31;
    unsigned cnt = min(g_candCount, (unsigned)CAND_CAP);

    for (unsigned j = t; j < cnt; j += NTHR) sc[j] = g_cand[j];
    __syncthreads();

    int gw = b * (NTHR / 32) + warpId;
    for (unsigned c = (unsigned)gw; c < cnt; c += NWARPS) {
        unsigned long long my = sc[c];
        unsigned r = 0;
        for (unsigned j = lane; j < cnt; j += 32) r += (sc[j] > my);
        r = __reduce_add_sync(0xffffffffu, r);
        if (r < K_TOP) {
            int i = (int)(~(unsigned)(my & 0xFFFFFFFFULL));
            int j = (int)r;
            const float4* row = (const float4*)(cls + (size_t)i * NCLS);
            unsigned long long bkey = 0ULL;
            if (lane < NCLS / 4) {
                float4 v = row[lane];
                float s0 = ref_sigmoid(v.x), s1 = ref_sigmoid(v.y);
                float s2 = ref_sigmoid(v.z), s3 = ref_sigmoid(v.w);
                unsigned long long k0 = ((unsigned long long)f2ord(s0) << 32) |
                                        (unsigned)(~(4 * lane + 0));
                unsigned long long k1 = ((unsigned long long)f2ord(s1) << 32) |
                                        (unsigned)(~(4 * lane + 1));
                unsigned long long k2 = ((unsigned long long)f2ord(s2) << 32) |
                                        (unsigned)(~(4 * lane + 2));
                unsigned long long k3 = ((unsigned long long)f2ord(s3) << 32) |
                                        (unsigned)(~(4 * lane + 3));
                bkey = max(max(k0, k1), max(k2, k3));
            }
#pragma unroll
            for (int off = 16; off >= 1; off >>= 1) {
                unsigned long long o = __shfl_xor_sync(0xffffffffu, bkey, off);
                if (o > bkey) bkey = o;
            }
            if (lane == 0) {
                float best = ord2f((unsigned)(bkey >> 32));
                int bl = (int)(~(unsigned)(bkey & 0xFFFFFFFFULL));
                float4 rg = ((const float4*)reg)[i];
                float4 an = ((const float4*)anc)[i];
                float ox = fminf(fmaxf(rg.x * an.z, -32.0f), 32.0f);
                float oy = fminf(fmaxf(rg.y * an.w, -32.0f), 32.0f);
                float cx = an.x + ox, cy = an.y + oy;
                float w = an.z * expf(fminf(rg.z, SCALE_CLAMP));
                float h = an.w * expf(fminf(rg.w, SCALE_CLAMP));
                float x1 = fminf(fmaxf((cx - 0.5f * w) * IMG_INV, 0.0f), 1.0f);
                float y1 = fminf(fmaxf((cy - 0.5f * h) * IMG_INV, 0.0f), 1.0f);
                float x2 = fminf(fmaxf((cx + 0.5f * w) * IMG_INV, 0.0f), 1.0f);
                float y2 = fminf(fmaxf((cy + 0.5f * h) * IMG_INV, 0.0f), 1.0f);
                out[4 * j + 0] = x1; out[4 * j + 1] = y1;
                out[4 * j + 2] = x2; out[4 * j + 3] = y2;
                out[4000 + j] = best;
                out[5000 + j] = (float)bl;
                g_boxes[j] = make_float4(x1, y1, x2, y2);
                g_labels[j] = bl;
                if (best >= 0.05f)
                    atomicOr(&g_validw[j >> 5], 1u << (j & 31));
            }
        }
    }
    // cleanup for next run: hist + colnz
    {
        int z = b * NTHR + t;
        if (z < NHBINS) g_hist[z] = 0u;
        if (b == 0 && t < 32) g_colnz[t] = 0u;
    }
}

// ---------------- K4: smem-staged mask + sync + sparse NMS ------------------
__global__ void __launch_bounds__(NTHR, 1)
k_end(float* __restrict__ out) {
    __shared__ float4   s_box[K_TOP];          // 16 KB
    __shared__ int      s_lab[K_TOP];          //  4 KB
    __shared__ unsigned s_list[1024];          //  4 KB
    __shared__ unsigned s_cols[CAPC * 32];     // 16 KB
    __shared__ unsigned s_C;
    const int t = threadIdx.x;
    const int b = blockIdx.x;
    const int warpId = t >> 5;
    const int lane = t & 31;

    // stage boxes + labels into smem (coalesced)
    for (int idx = t; idx < K_TOP; idx += NTHR) {
        s_box[idx] = g_boxes[idx];
        s_lab[idx] = g_labels[idx];
    }
    __syncthreads();

    // mask + column-nonzero bitset (all loads now LDS)
    {
        int gw = b * (NTHR / 32) + warpId;
        for (int task = gw; task < K_TOP * 32; task += GRID_R * (NTHR / 32)) {
            int i = task >> 5, W = task & 31;
            float4 bi = s_box[i];
            int li = s_lab[i];
            float ai = (bi.z - bi.x) * (bi.w - bi.y);
            int j = W * 32 + lane;
            bool sup = false;
            if (j < i && s_lab[j] == li) {
                float4 bj = s_box[j];
                float xx1 = fmaxf(bi.x, bj.x), yy1 = fmaxf(bi.y, bj.y);
                float xx2 = fminf(bi.z, bj.z), yy2 = fminf(bi.w, bj.w);
                float ww = fmaxf(1e-10f, xx2 - xx1);
                float hh = fmaxf(1e-10f, yy2 - yy1);
                float inter = ww * hh;
                float aj = (bj.z - bj.x) * (bj.w - bj.y);
                float iou = inter / (ai + aj - inter + 1e-10f);
                sup = iou > 0.6f;
            }
            unsigned bits = __ballot_sync(0xffffffffu, sup);
            if (lane == 0) {
                g_mask[task] = bits;
                if (bits) atomicOr(&g_colnz[i >> 5], 1u << (i & 31));
            }
        }
        if (b == 5 && t == 0) g_candCount = 0u;
    }
    gridsync(1, 1);   // FINAL: resets g_barrier
    if (b != 0) return;

    // build ordered nonzero-column list (warp 0)
    if (t < 32) {
        unsigned cz = g_colnz[t];
        unsigned pc = __popc(cz);
        unsigned pre = pc;
#pragma unroll
        for (int off = 1; off < 32; off <<= 1) {
            unsigned v = __shfl_up_sync(0xffffffffu, pre, off);
            if (lane >= off) pre += v;
        }
        unsigned start = pre - pc;              // exclusive prefix
        unsigned word = cz, k = 0;
        while (word) {
            int bbit = __ffs(word) - 1;
            word &= word - 1u;
            s_list[start + k] = (unsigned)(t * 32 + bbit);
            k++;
        }
        if (t == 31) s_C = pre;
    }
    __syncthreads();
    unsigned C = s_C;

    // stage the first min(C, CAPC) suppression columns into smem
    unsigned CS = min(C, (unsigned)CAPC);
    for (unsigned idx = t; idx < CS * 32; idx += NTHR) {
        unsigned k = idx >> 5, l2 = idx & 31;
        s_cols[idx] = g_mask[s_list[k] * 32 + l2];
    }
    __syncthreads();

    // serial greedy over nonzero columns only (warp 0)
    if (t < 32) {
        unsigned vw = g_validw[t];
        unsigned cz = g_colnz[t];
        unsigned kw = vw & ~cz;                 // zero-column: keep = valid
        for (unsigned k = 0; k < C; k++) {
            unsigned i = s_list[k];
            unsigned colw = (k < CAPC) ? s_cols[k * 32 + t]
                                       : g_mask[i * 32 + t];
            bool ov = __any_sync(0xffffffffu, (colw & kw) != 0u);
            unsigned vb = (__shfl_sync(0xffffffffu, vw, i >> 5) >> (i & 31)) & 1u;
            bool kp = (vb != 0u) && !ov;
            if (kp && (unsigned)t == (i >> 5)) kw |= (1u << (i & 31));
        }
#pragma unroll
        for (int e = 0; e < 32; e++) {
            int i = t * 32 + e;
            if (i < K_TOP) out[6000 + i] = ((kw >> e) & 1u) ? 1.0f : 0.0f;
        }
    }
}

// ---------------- launcher ---------------------------------------------------
extern "C" void kernel_launch(void* const* d_in, const int* in_sizes, int n_in,
                              void* d_out, int out_size) {
    const float* cls = (const float*)d_in[0];
    const float* reg = (const float*)d_in[1];
    const float* anc = (const float*)d_in[2];
    float* out = (float*)d_out;
    (void)in_sizes; (void)n_in; (void)out_size;

    cudaFuncSetAttribute(k_rank, cudaFuncAttributeMaxDynamicSharedMemorySize,
                         CAND_CAP * (int)sizeof(unsigned long long));

    k_p1<<<GRID_P1, NTHR>>>(cls);
    k_sel<<<GRID_R, NTHR>>>();
    k_rank<<<GRID_R, NTHR, CAND_CAP * sizeof(unsigned long long)>>>(cls, reg, anc, out);
    k_end<<<GRID_R, NTHR>>>(out);
}